// round 15
// baseline (speedup 1.0000x reference)
#include <cuda_runtime.h>
#include <cuda_fp16.h>
#include <cstdint>

typedef unsigned int u32;
typedef unsigned long long u64t;

// ============================================================================
// g_prep: packed, fragment-ordered fp16 W1 (single precision weights).
// [kc 0..23][br 0..1][n 0..95][q 0..3] -> 16B uint4 (both k16 steps)
// ============================================================================
__device__ __align__(16) u32 g_prep[24 * 2 * 96 * 16];   // 294912 B

__device__ __forceinline__ u32 pack_half(float a, float b) {
    __half2 h = __floats2half2_rn(a, b);
    return *(u32*)&h;
}

__global__ void prep_w1(const float* __restrict__ eW1, const float* __restrict__ sW1)
{
    int idx = blockIdx.x * 256 + threadIdx.x;        // 0 .. 18431
    if (idx >= 18432) return;
    int q  = idx & 3;
    int n  = (idx >> 2) % 96;
    int t  = (idx >> 2) / 96;
    int kc = t % 24;
    int br = t / 24;
    const float* W = (br ? sW1 : eW1) + (size_t)n * 768 + kc * 32;
    uint4 v;
    v.x = pack_half(W[2*q],      W[2*q+1]);
    v.y = pack_half(W[8+2*q],    W[8+2*q+1]);
    v.z = pack_half(W[16+2*q],   W[16+2*q+1]);
    v.w = pack_half(W[24+2*q],   W[24+2*q+1]);
    u32 off = (u32)kc * 12288 + (u32)br * 6144 + (u32)n * 64 + (u32)q * 16;
    *(uint4*)((char*)g_prep + off) = v;
}

// ============================================================================
// helpers
// ============================================================================
__device__ __forceinline__ u32 smem_u32(const void* p) {
    u32 a;
    asm("{ .reg .u64 t; cvta.to.shared.u64 t, %1; cvt.u32.u64 %0, t; }" : "=r"(a) : "l"(p));
    return a;
}
__device__ __forceinline__ u64t fma2(u64t a, u64t b, u64t c) {
    u64t d;
    asm("fma.rn.f32x2 %0, %1, %2, %3;" : "=l"(d) : "l"(a), "l"(b), "l"(c));
    return d;
}
__device__ __forceinline__ float red2(u64t v) {
    return __uint_as_float((u32)v) + __uint_as_float((u32)(v >> 32));
}
__device__ __forceinline__ u64t pack2(float lo, float hi) {
    return (u64t)__float_as_uint(lo) | ((u64t)__float_as_uint(hi) << 32);
}
// fp16 pack of 4 floats (single precision plane)
__device__ __forceinline__ u64t half4(float4 q) {
    __half2 h01 = __floats2half2_rn(q.x, q.y);
    __half2 h23 = __floats2half2_rn(q.z, q.w);
    return (u64t)(*(u32*)&h01) | ((u64t)(*(u32*)&h23) << 32);
}
__device__ __forceinline__ void mma_f16(float c[4], u32 a0, u32 a1, u32 a2, u32 a3,
                                        u32 b0, u32 b1) {
    asm volatile("mma.sync.aligned.m16n8k16.row.col.f32.f16.f16.f32 "
        "{%0,%1,%2,%3}, {%4,%5,%6,%7}, {%8,%9}, {%0,%1,%2,%3};"
        : "+f"(c[0]), "+f"(c[1]), "+f"(c[2]), "+f"(c[3])
        : "r"(a0), "r"(a1), "r"(a2), "r"(a3), "r"(b0), "r"(b1));
}
#define LDSM_X4(d0, d1, d2, d3, a) \
    asm volatile("ldmatrix.sync.aligned.m8n8.x4.shared.b16 {%0,%1,%2,%3}, [%4];" \
        : "=r"(d0), "=r"(d1), "=r"(d2), "=r"(d3) : "r"(a))

// ============================================================================
// smem layout (bytes), per 256-thread CTA (1 CTA/SM), 64 batch rows
//   A stages: stage*20480 ; per stage: e rows [0,10240), s rows [10240,20480)
//             vec row layout: off = rb*160 + {0:pair_e, 80:seq_e} (+10240 for s)
//   B stages: 40960 + stage*12288  -> ends 65536
//   tail overlay: y1 [0, 102400) = 256 vec rows * 100 f ; weights at 102400
// ============================================================================
#define A_STAGE 20480
#define SM_B0   40960
#define B_STAGE 12288
#define SM_W    102400
#define SMEM_BYTES 152464
// weight region float offsets (from sm + SM_W)
#define OW2E 0
#define OW2S 4608
#define OW3E 9216
#define OW3S 10368
#define OW4E 11520
#define OW4S 11808
#define OW5  12096
#define OE5  12120
#define OSE  12132
#define OT0  12260
#define OT1  12388

__global__ __launch_bounds__(256, 1) void fused_mma(
    const float* __restrict__ in,
    const float* __restrict__ sW2, const float* __restrict__ sW3,
    const float* __restrict__ sW4, const float* __restrict__ sW5,
    const float* __restrict__ eW2, const float* __restrict__ eW3,
    const float* __restrict__ eW4, const float* __restrict__ eW5,
    const float* __restrict__ s_seq, const float* __restrict__ s_pair,
    const float* __restrict__ e_seq, const float* __restrict__ e_pair,
    const float* __restrict__ cross_w,
    float* __restrict__ out)
{
    extern __shared__ __align__(1024) char sm[];
    float* y1f = (float*)sm;
    float* wf  = (float*)(sm + SM_W);

    const int tid = threadIdx.x;
    const int r0g = blockIdx.x * 64;

    const float ep0 = e_pair[0], ep1 = e_pair[1];
    const float sp0 = s_pair[0], sp1 = s_pair[1];
    const float es0 = e_seq[0], es1 = e_seq[1], es2 = e_seq[2], es3 = e_seq[3];
    const float ss0 = s_seq[0], ss1 = s_seq[1], ss2 = s_seq[2], ss3 = s_seq[3];

    // ---- builder mapping: rows rb and rb+32 per thread ----
    const int rb = tid >> 3;           // 0..31
    const int sk = tid & 7;            // float4 group within 32-k chunk
    const float* inp0 = in + (size_t)(r0g + rb) * 3072 + sk * 4;
    const float* inp1 = inp0 + (size_t)32 * 3072;

    // ---- mma mapping: 8 warps, warp = m64 x n48 (4 m-blocks) ----
    const int lane = tid & 31;
    const int w    = tid >> 5;          // 0..7
    const int br   = w >> 2;            // 0=e, 1=s
    const int wm   = (w >> 1) & 1;      // m64 group within branch
    const int nh   = w & 1;             // n half
    const int fr   = lane >> 2;
    const int ql   = lane & 3;

    // ldmatrix lane addressing (canonical m16k16 x4)
    const u32 lrow = (u32)((lane & 7) | (((lane >> 3) & 1) << 3));   // 0..15
    const u32 lkb  = (u32)((lane >> 4) * 16);                        // 0 or 16 B

    u64t gprep;
    asm("cvta.to.global.u64 %0, %1;" : "=l"(gprep) : "l"((const void*)g_prep));
    const u32 smbase = smem_u32(sm);
    const u32 b_sm = smbase + SM_B0;
    // warp's A base (within a stage): branch + wm*64 rows
    const u32 awarp = (u32)(br * 10240) + (u32)(wm * 64 + lrow) * 80 + lkb;

    float acc[4][6][4];
#pragma unroll
    for (int im = 0; im < 4; im++)
#pragma unroll
        for (int nf = 0; nf < 6; nf++)
#pragma unroll
            for (int c = 0; c < 4; c++) acc[im][nf][c] = 0.f;

    float4 sA0, sA1, sA2, sA3, sB0, sB1, sB2, sB3;

#define LOAD_STAGE(kcv) { \
    const float* p0 = inp0 + (kcv) * 32; \
    sA0 = *(const float4*)p0; sA1 = *(const float4*)(p0 + 768); \
    sA2 = *(const float4*)(p0 + 1536); sA3 = *(const float4*)(p0 + 2304); \
    const float* p1 = inp1 + (kcv) * 32; \
    sB0 = *(const float4*)p1; sB1 = *(const float4*)(p1 + 768); \
    sB2 = *(const float4*)(p1 + 1536); sB3 = *(const float4*)(p1 + 2304); }

#define BUILD_ONE(stage, roff, t0, t1, t2, t3) { \
    u32 off = (u32)(stage) * A_STAGE + (u32)(roff) * 160 + (u32)sk * 8; \
    float4 q; \
    q.x = fmaxf(ep0*t0.x + ep1*t2.x, 0.f); q.y = fmaxf(ep0*t0.y + ep1*t2.y, 0.f); \
    q.z = fmaxf(ep0*t0.z + ep1*t2.z, 0.f); q.w = fmaxf(ep0*t0.w + ep1*t2.w, 0.f); \
    *(u64t*)(sm + off) = half4(q); \
    q.x = fmaxf(es0*t0.x + es1*t1.x + es2*t2.x + es3*t3.x, 0.f); \
    q.y = fmaxf(es0*t0.y + es1*t1.y + es2*t2.y + es3*t3.y, 0.f); \
    q.z = fmaxf(es0*t0.z + es1*t1.z + es2*t2.z + es3*t3.z, 0.f); \
    q.w = fmaxf(es0*t0.w + es1*t1.w + es2*t2.w + es3*t3.w, 0.f); \
    *(u64t*)(sm + off + 80) = half4(q); \
    q.x = fmaxf(sp0*t0.x + sp1*t2.x, 0.f); q.y = fmaxf(sp0*t0.y + sp1*t2.y, 0.f); \
    q.z = fmaxf(sp0*t0.z + sp1*t2.z, 0.f); q.w = fmaxf(sp0*t0.w + sp1*t2.w, 0.f); \
    *(u64t*)(sm + off + 10240) = half4(q); \
    q.x = fmaxf(ss0*t0.x + ss1*t1.x + ss2*t2.x + ss3*t3.x, 0.f); \
    q.y = fmaxf(ss0*t0.y + ss1*t1.y + ss2*t2.y + ss3*t3.y, 0.f); \
    q.z = fmaxf(ss0*t0.z + ss1*t1.z + ss2*t2.z + ss3*t3.z, 0.f); \
    q.w = fmaxf(ss0*t0.w + ss1*t1.w + ss2*t2.w + ss3*t3.w, 0.f); \
    *(u64t*)(sm + off + 10320) = half4(q); }

#define BUILD_STAGE(stage) { \
    BUILD_ONE(stage, rb, sA0, sA1, sA2, sA3); \
    BUILD_ONE(stage, rb + 32, sB0, sB1, sB2, sB3); }

#define CPASYNC_B(stage, kcv) { \
    u64t gs = gprep + (u64t)(kcv) * 12288; \
    u32 db = b_sm + (u32)(stage) * B_STAGE; \
    _Pragma("unroll") \
    for (int j = 0; j < 3; j++) { \
        u32 i = (u32)tid * 16 + (u32)j * 4096; \
        asm volatile("cp.async.cg.shared.global [%0], [%1], 16;" \
                     :: "r"(db + i), "l"(gs + i) : "memory"); \
    } \
    asm volatile("cp.async.commit_group;" ::: "memory"); }

    // ---- prologue ----
    LOAD_STAGE(0);
    BUILD_STAGE(0);
    CPASYNC_B(0, 0);
    LOAD_STAGE(1);
    asm volatile("cp.async.wait_group 0;" ::: "memory");
    __syncthreads();

    // ---- mainloop (branchless body, 2 stages) ----
    for (int kc = 0; kc < 24; kc++) {
        const int cur = kc & 1, nxt = cur ^ 1;
        const int kn = (kc < 23) ? kc + 1 : 23;
        const int kl = (kc < 22) ? kc + 2 : 23;
        const u32 bbase = b_sm + (u32)cur * B_STAGE + (u32)(br * 6144 + nh * 3072)
                        + (u32)fr * 64 + (u32)ql * 16;

        CPASYNC_B(nxt, kn);        // B for next chunk: latency hides under body

        // load all B fragments for this chunk (both k16 steps packed per uint4)
        uint4 bv[6];
#pragma unroll
        for (int nf = 0; nf < 6; nf++)
            bv[nf] = *(const uint4*)(sm + (bbase - smbase) + nf * 512);

        // k16 step 0 (B frags bv.x, bv.y) — 4 m-blocks
        {
            u32 aB = smbase + (u32)cur * A_STAGE + awarp;
            u32 ah[4][4];
#pragma unroll
            for (int i = 0; i < 4; i++)
                LDSM_X4(ah[i][0], ah[i][1], ah[i][2], ah[i][3], aB + (u32)i * 1280);
#pragma unroll
            for (int nf = 0; nf < 6; nf++)
#pragma unroll
                for (int im = 0; im < 4; im++)
                    mma_f16(acc[im][nf], ah[im][0], ah[im][1], ah[im][2], ah[im][3],
                            bv[nf].x, bv[nf].y);
        }
        BUILD_STAGE(nxt);          // A for next chunk (from prefetched regs)
        // k16 step 1 (B frags bv.z, bv.w)
        {
            u32 aB = smbase + (u32)cur * A_STAGE + awarp + 32;
            u32 ah[4][4];
#pragma unroll
            for (int i = 0; i < 4; i++)
                LDSM_X4(ah[i][0], ah[i][1], ah[i][2], ah[i][3], aB + (u32)i * 1280);
#pragma unroll
            for (int nf = 0; nf < 6; nf++)
#pragma unroll
                for (int im = 0; im < 4; im++)
                    mma_f16(acc[im][nf], ah[im][0], ah[im][1], ah[im][2], ah[im][3],
                            bv[nf].z, bv[nf].w);
        }
        LOAD_STAGE(kl);            // LDG prefetch for chunk kc+2
        asm volatile("cp.async.wait_group 0;" ::: "memory");
        __syncthreads();
    }

    // ---- epilogue: relu(y1) -> [256 vec rows][100] (overlays dead stage smem) ----
#pragma unroll
    for (int im = 0; im < 4; im++) {
        int m0 = br * 128 + (wm * 4 + im) * 16 + fr;
        int m1 = m0 + 8;
#pragma unroll
        for (int nf = 0; nf < 6; nf++) {
            int nb = (nh * 6 + nf) * 8 + ql * 2;
            *(u64t*)(y1f + m0 * 100 + nb) = pack2(fmaxf(acc[im][nf][0], 0.f), fmaxf(acc[im][nf][1], 0.f));
            *(u64t*)(y1f + m1 * 100 + nb) = pack2(fmaxf(acc[im][nf][2], 0.f), fmaxf(acc[im][nf][3], 0.f));
        }
    }
    // tail weights into overlay region (disjoint from y1)
    for (int i = tid; i < 4608; i += 256) { wf[OW2E + i] = eW2[i]; wf[OW2S + i] = sW2[i]; }
    for (int i = tid; i < 1152; i += 256) { wf[OW3E + i] = eW3[i]; wf[OW3S + i] = sW3[i]; }
    if (tid < 144) { wf[OW4E + tid] = eW4[tid]; wf[OW4E + 144 + tid] = eW4[144 + tid];
                     wf[OW4S + tid] = sW4[tid]; wf[OW4S + 144 + tid] = sW4[144 + tid]; }
    if (tid >= 160 && tid < 184) wf[OW5 + tid - 160] = sW5[tid - 160];
    if (tid >= 192 && tid < 204) {
        int k = tid - 192; float s = 0.f;
#pragma unroll
        for (int h = 0; h < 8; h++) s += eW5[h * 12 + k];
        wf[OE5 + k] = s;
    }
    __syncthreads();

    // ---- tail: 2 passes, 2 threads per vector, k-split + shfl combine ----
#pragma unroll
    for (int pass = 0; pass < 2; pass++) {
        const int m  = pass * 128 + (tid >> 1);   // 0..255 vec row
        const int kh = tid & 1;                    // k half
        const bool is_e = m < 128;
        const int r  = (m & 127) >> 1;
        const int vp = m & 1;

        u64t x[24];
        const u64t* xr = (const u64t*)(y1f + m * 100 + kh * 48);
#pragma unroll
        for (int i = 0; i < 24; i++) x[i] = xr[i];

        const float* W2 = wf + (is_e ? OW2E : OW2S) + kh * 48;
        float y2r[48];
#pragma unroll 4
        for (int n = 0; n < 48; n++) {
            const u64t* wr = (const u64t*)(W2 + n * 96);
            u64t s0 = 0, s1 = 0;
#pragma unroll
            for (int kp = 0; kp < 24; kp += 2) {
                s0 = fma2(x[kp], wr[kp], s0);
                s1 = fma2(x[kp + 1], wr[kp + 1], s1);
            }
            float s = red2(s0) + red2(s1);
            s += __shfl_xor_sync(0xffffffffu, s, 1);
            y2r[n] = fmaxf(s, 0.f);
        }

        u64t b2[12];
#pragma unroll
        for (int j = 0; j < 12; j++) b2[j] = pack2(y2r[kh * 24 + 2 * j], y2r[kh * 24 + 2 * j + 1]);
        const float* W3 = wf + (is_e ? OW3E : OW3S) + kh * 24;
        float y3r[24];
#pragma unroll
        for (int n = 0; n < 24; n++) {
            const u64t* wr = (const u64t*)(W3 + n * 48);
            u64t s0 = 0;
#pragma unroll
            for (int kp = 0; kp < 12; kp++) s0 = fma2(b2[kp], wr[kp], s0);
            float s = red2(s0);
            s += __shfl_xor_sync(0xffffffffu, s, 1);
            y3r[n] = fmaxf(s, 0.f);
        }

        u64t b3[6];
#pragma unroll
        for (int j = 0; j < 6; j++) b3[j] = pack2(y3r[kh * 12 + 2 * j], y3r[kh * 12 + 2 * j + 1]);
        const float* W4 = wf + (is_e ? OW4E : OW4S) + kh * 12;
        float r4[12];
#pragma unroll
        for (int n = 0; n < 12; n++) {
            const u64t* wr = (const u64t*)(W4 + n * 24);
            u64t s0 = 0;
#pragma unroll
            for (int kp = 0; kp < 6; kp++) s0 = fma2(b3[kp], wr[kp], s0);
            float s = red2(s0);
            s += __shfl_xor_sync(0xffffffffu, s, 1);
            r4[n] = fmaxf(s, 0.f);       // relu before W5
        }

        if (kh == 0) {
            const int idx2 = r * 2 + vp;
            if (is_e) {
                float Se = 0.f;
#pragma unroll
                for (int k = 0; k < 12; k++) Se = fmaf(r4[k], wf[OE5 + k], Se);
                wf[OSE + idx2] = Se;
            } else {
                float t0 = 0.f, t1 = 0.f;
#pragma unroll
                for (int k = 0; k < 12; k++) {
                    t0 = fmaf(r4[k], wf[OW5 + k], t0);
                    t1 = fmaf(r4[k], wf[OW5 + 12 + k], t1);
                }
                wf[OT0 + idx2] = t0;
                wf[OT1 + idx2] = t1;
            }
        }
    }
    __syncthreads();

    if (tid < 64) {
        const int r = tid;
        const float cw0 = cross_w[0], cw1 = cross_w[1];
        float SeP = wf[OSE + 2*r], SeS = wf[OSE + 2*r + 1];
        float o0 = cw0 * SeP * wf[OT0 + 2*r] + cw1 * SeS * wf[OT0 + 2*r + 1];
        float o1 = cw0 * SeP * wf[OT1 + 2*r] + cw1 * SeS * wf[OT1 + 2*r + 1];
        out[(size_t)(r0g + r) * 2 + 0] = o0;
        out[(size_t)(r0g + r) * 2 + 1] = o1;
    }
}

// ============================================================================
extern "C" void kernel_launch(void* const* d_in, const int* in_sizes, int n_in,
                              void* d_out, int out_size)
{
    const float* in      = (const float*)d_in[0];
    const float* sW1     = (const float*)d_in[1];
    const float* sW2     = (const float*)d_in[2];
    const float* sW3     = (const float*)d_in[3];
    const float* sW4     = (const float*)d_in[4];
    const float* sW5     = (const float*)d_in[5];
    const float* eW1     = (const float*)d_in[6];
    const float* eW2     = (const float*)d_in[7];
    const float* eW3     = (const float*)d_in[8];
    const float* eW4     = (const float*)d_in[9];
    const float* eW5     = (const float*)d_in[10];
    const float* s_seq   = (const float*)d_in[11];
    const float* s_pair  = (const float*)d_in[12];
    const float* e_seq   = (const float*)d_in[13];
    const float* e_pair  = (const float*)d_in[14];
    const float* cross_w = (const float*)d_in[15];
    float* out = (float*)d_out;

    const int B = in_sizes[0] / 3072;   // 65536

    static int init_done = 0;
    if (!init_done) {
        cudaFuncSetAttribute(fused_mma, cudaFuncAttributeMaxDynamicSharedMemorySize, SMEM_BYTES);
        init_done = 1;
    }
    prep_w1<<<72, 256>>>(eW1, sW1);
    fused_mma<<<B / 64, 256, SMEM_BYTES>>>(
        in, sW2, sW3, sW4, sW5, eW2, eW3, eW4, eW5,
        s_seq, s_pair, e_seq, e_pair, cross_w, out);
}

// round 16
// speedup vs baseline: 1.2464x; 1.2464x over previous
#include <cuda_runtime.h>
#include <cuda_fp16.h>
#include <cstdint>

typedef unsigned int u32;
typedef unsigned long long u64t;

// ============================================================================
// g_prep: packed, fragment-ordered fp16 W1 (single precision weights).
// [kc 0..23][br 0..1][n 0..95][q 0..3] -> 16B uint4 (both k16 steps)
// ============================================================================
__device__ __align__(16) u32 g_prep[24 * 2 * 96 * 16];   // 294912 B

__device__ __forceinline__ u32 pack_half(float a, float b) {
    __half2 h = __floats2half2_rn(a, b);
    return *(u32*)&h;
}

__global__ void prep_w1(const float* __restrict__ eW1, const float* __restrict__ sW1)
{
    int idx = blockIdx.x * 256 + threadIdx.x;        // 0 .. 18431
    if (idx >= 18432) return;
    int q  = idx & 3;
    int n  = (idx >> 2) % 96;
    int t  = (idx >> 2) / 96;
    int kc = t % 24;
    int br = t / 24;
    const float* W = (br ? sW1 : eW1) + (size_t)n * 768 + kc * 32;
    uint4 v;
    v.x = pack_half(W[2*q],      W[2*q+1]);
    v.y = pack_half(W[8+2*q],    W[8+2*q+1]);
    v.z = pack_half(W[16+2*q],   W[16+2*q+1]);
    v.w = pack_half(W[24+2*q],   W[24+2*q+1]);
    u32 off = (u32)kc * 12288 + (u32)br * 6144 + (u32)n * 64 + (u32)q * 16;
    *(uint4*)((char*)g_prep + off) = v;
}

// ============================================================================
// helpers
// ============================================================================
__device__ __forceinline__ u32 smem_u32(const void* p) {
    u32 a;
    asm("{ .reg .u64 t; cvta.to.shared.u64 t, %1; cvt.u32.u64 %0, t; }" : "=r"(a) : "l"(p));
    return a;
}
__device__ __forceinline__ u64t fma2(u64t a, u64t b, u64t c) {
    u64t d;
    asm("fma.rn.f32x2 %0, %1, %2, %3;" : "=l"(d) : "l"(a), "l"(b), "l"(c));
    return d;
}
__device__ __forceinline__ float red2(u64t v) {
    return __uint_as_float((u32)v) + __uint_as_float((u32)(v >> 32));
}
__device__ __forceinline__ u64t pack2(float lo, float hi) {
    return (u64t)__float_as_uint(lo) | ((u64t)__float_as_uint(hi) << 32);
}
// fp16 pack of 4 floats (single precision plane)
__device__ __forceinline__ u64t half4(float4 q) {
    __half2 h01 = __floats2half2_rn(q.x, q.y);
    __half2 h23 = __floats2half2_rn(q.z, q.w);
    return (u64t)(*(u32*)&h01) | ((u64t)(*(u32*)&h23) << 32);
}
__device__ __forceinline__ void mma_f16(float c[4], u32 a0, u32 a1, u32 a2, u32 a3,
                                        u32 b0, u32 b1) {
    asm volatile("mma.sync.aligned.m16n8k16.row.col.f32.f16.f16.f32 "
        "{%0,%1,%2,%3}, {%4,%5,%6,%7}, {%8,%9}, {%0,%1,%2,%3};"
        : "+f"(c[0]), "+f"(c[1]), "+f"(c[2]), "+f"(c[3])
        : "r"(a0), "r"(a1), "r"(a2), "r"(a3), "r"(b0), "r"(b1));
}
#define LDSM_X4(d0, d1, d2, d3, a) \
    asm volatile("ldmatrix.sync.aligned.m8n8.x4.shared.b16 {%0,%1,%2,%3}, [%4];" \
        : "=r"(d0), "=r"(d1), "=r"(d2), "=r"(d3) : "r"(a))

// ============================================================================
// smem layout (bytes), per 256-thread CTA (2 CTAs/SM)
//   A stages: stage*10240 (128 vec rows * 80B, fp16 single plane)
//   B stages: 20480 + stage*12288  -> ends 45056
//   tail overlay: y1 fp16 [0, 28672) = 128 rows * 112 halfs ; weights at 28672
// ============================================================================
#define A_STAGE 10240
#define SM_B0   20480
#define B_STAGE 12288
#define SM_W    28672
#define SMEM_BYTES 78080
// weight region float offsets (from sm + SM_W)
#define OW2E 0
#define OW2S 4608
#define OW3E 9216
#define OW3S 10368
#define OW4E 11520
#define OW4S 11808
#define OW5  12096
#define OE5  12120
#define OSE  12132
#define OT0  12196
#define OT1  12260

__global__ __launch_bounds__(256, 2) void fused_mma(
    const float* __restrict__ in,
    const float* __restrict__ sW2, const float* __restrict__ sW3,
    const float* __restrict__ sW4, const float* __restrict__ sW5,
    const float* __restrict__ eW2, const float* __restrict__ eW3,
    const float* __restrict__ eW4, const float* __restrict__ eW5,
    const float* __restrict__ s_seq, const float* __restrict__ s_pair,
    const float* __restrict__ e_seq, const float* __restrict__ e_pair,
    const float* __restrict__ cross_w,
    float* __restrict__ out)
{
    extern __shared__ __align__(1024) char sm[];
    float* wf = (float*)(sm + SM_W);

    const int tid = threadIdx.x;
    const int r0g = blockIdx.x * 32;

    const float ep0 = e_pair[0], ep1 = e_pair[1];
    const float sp0 = s_pair[0], sp1 = s_pair[1];
    const float es0 = e_seq[0], es1 = e_seq[1], es2 = e_seq[2], es3 = e_seq[3];
    const float ss0 = s_seq[0], ss1 = s_seq[1], ss2 = s_seq[2], ss3 = s_seq[3];

    // ---- builder mapping: 32 rows across 256 threads ----
    const int rb = tid >> 3;           // 0..31 batch row
    const int sk = tid & 7;            // float4 group within 32-k chunk
    const float* inp0 = in + (size_t)(r0g + rb) * 3072 + sk * 4;

    // ---- mma mapping: 8 warps, warp = m32 x n48 ----
    const int lane = tid & 31;
    const int w    = tid >> 5;          // 0..7
    const int br   = w >> 2;            // 0=e, 1=s
    const int wm   = (w >> 1) & 1;      // m32 group within branch
    const int nh   = w & 1;             // n half
    const int fr   = lane >> 2;
    const int ql   = lane & 3;
    const int mb0  = br * 4 + wm * 2;   // first m16 block (0..7)

    // ldmatrix lane addressing (canonical m16k16 x4)
    const u32 lrow = (u32)((lane & 7) | (((lane >> 3) & 1) << 3));   // 0..15
    const u32 lkb  = (u32)((lane >> 4) * 16);                        // 0 or 16 B

    u64t gprep;
    asm("cvta.to.global.u64 %0, %1;" : "=l"(gprep) : "l"((const void*)g_prep));
    const u32 smbase = smem_u32(sm);
    const u32 b_sm = smbase + SM_B0;

    float acc[2][6][4];
#pragma unroll
    for (int im = 0; im < 2; im++)
#pragma unroll
        for (int nf = 0; nf < 6; nf++)
#pragma unroll
            for (int c = 0; c < 4; c++) acc[im][nf][c] = 0.f;

    float4 sA0, sA1, sA2, sA3;

#define LOAD_STAGE(kcv) { \
    const float* p0 = inp0 + (kcv) * 32; \
    sA0 = __ldcg((const float4*)p0);          sA1 = __ldcg((const float4*)(p0 + 768)); \
    sA2 = __ldcg((const float4*)(p0 + 1536)); sA3 = __ldcg((const float4*)(p0 + 2304)); }

#define BUILD_STAGE(stage) { \
    u32 off = (u32)(stage) * A_STAGE + (u32)rb * 160 + (u32)sk * 8; \
    float4 q; \
    q.x = fmaxf(ep0*sA0.x + ep1*sA2.x, 0.f); q.y = fmaxf(ep0*sA0.y + ep1*sA2.y, 0.f); \
    q.z = fmaxf(ep0*sA0.z + ep1*sA2.z, 0.f); q.w = fmaxf(ep0*sA0.w + ep1*sA2.w, 0.f); \
    *(u64t*)(sm + off) = half4(q); \
    q.x = fmaxf(es0*sA0.x + es1*sA1.x + es2*sA2.x + es3*sA3.x, 0.f); \
    q.y = fmaxf(es0*sA0.y + es1*sA1.y + es2*sA2.y + es3*sA3.y, 0.f); \
    q.z = fmaxf(es0*sA0.z + es1*sA1.z + es2*sA2.z + es3*sA3.z, 0.f); \
    q.w = fmaxf(es0*sA0.w + es1*sA1.w + es2*sA2.w + es3*sA3.w, 0.f); \
    *(u64t*)(sm + off + 80) = half4(q); \
    q.x = fmaxf(sp0*sA0.x + sp1*sA2.x, 0.f); q.y = fmaxf(sp0*sA0.y + sp1*sA2.y, 0.f); \
    q.z = fmaxf(sp0*sA0.z + sp1*sA2.z, 0.f); q.w = fmaxf(sp0*sA0.w + sp1*sA2.w, 0.f); \
    *(u64t*)(sm + off + 5120) = half4(q); \
    q.x = fmaxf(ss0*sA0.x + ss1*sA1.x + ss2*sA2.x + ss3*sA3.x, 0.f); \
    q.y = fmaxf(ss0*sA0.y + ss1*sA1.y + ss2*sA2.y + ss3*sA3.y, 0.f); \
    q.z = fmaxf(ss0*sA0.z + ss1*sA1.z + ss2*sA2.z + ss3*sA3.z, 0.f); \
    q.w = fmaxf(ss0*sA0.w + ss1*sA1.w + ss2*sA2.w + ss3*sA3.w, 0.f); \
    *(u64t*)(sm + off + 5200) = half4(q); }

#define CPASYNC_B(stage, kcv) { \
    u64t gs = gprep + (u64t)(kcv) * 12288; \
    u32 db = b_sm + (u32)(stage) * B_STAGE; \
    _Pragma("unroll") \
    for (int j = 0; j < 3; j++) { \
        u32 i = (u32)tid * 16 + (u32)j * 4096; \
        asm volatile("cp.async.cg.shared.global [%0], [%1], 16;" \
                     :: "r"(db + i), "l"(gs + i) : "memory"); \
    } \
    asm volatile("cp.async.commit_group;" ::: "memory"); }

    // ---- prologue ----
    LOAD_STAGE(0);
    BUILD_STAGE(0);
    CPASYNC_B(0, 0);
    LOAD_STAGE(1);
    asm volatile("cp.async.wait_group 0;" ::: "memory");
    __syncthreads();

    // ---- mainloop (branchless body, 2 stages) ----
    for (int kc = 0; kc < 24; kc++) {
        const int cur = kc & 1, nxt = cur ^ 1;
        const int kn = (kc < 23) ? kc + 1 : 23;
        const int kl = (kc < 22) ? kc + 2 : 23;
        const u32 bbase = b_sm + (u32)cur * B_STAGE + (u32)(br * 6144 + nh * 3072)
                        + (u32)fr * 64 + (u32)ql * 16;

        CPASYNC_B(nxt, kn);        // B for next chunk: latency hides under body

        // load all B fragments for this chunk (both k16 steps packed per uint4)
        uint4 bv[6];
#pragma unroll
        for (int nf = 0; nf < 6; nf++)
            bv[nf] = *(const uint4*)(sm + (bbase - smbase) + nf * 512);

        // k16 step 0 (B frags bv.x, bv.y)
        {
            u32 aB = smbase + (u32)cur * A_STAGE + (u32)(mb0 * 16 + lrow) * 80 + lkb;
            u32 ah0[4], ah1[4];
            LDSM_X4(ah0[0], ah0[1], ah0[2], ah0[3], aB);
            LDSM_X4(ah1[0], ah1[1], ah1[2], ah1[3], aB + 1280);
#pragma unroll
            for (int nf = 0; nf < 6; nf++) {
                mma_f16(acc[0][nf], ah0[0], ah0[1], ah0[2], ah0[3], bv[nf].x, bv[nf].y);
                mma_f16(acc[1][nf], ah1[0], ah1[1], ah1[2], ah1[3], bv[nf].x, bv[nf].y);
            }
        }
        BUILD_STAGE(nxt);          // A for next chunk (from prefetched regs)
        // k16 step 1 (B frags bv.z, bv.w)
        {
            u32 aB = smbase + (u32)cur * A_STAGE + (u32)(mb0 * 16 + lrow) * 80 + lkb + 32;
            u32 ah0[4], ah1[4];
            LDSM_X4(ah0[0], ah0[1], ah0[2], ah0[3], aB);
            LDSM_X4(ah1[0], ah1[1], ah1[2], ah1[3], aB + 1280);
#pragma unroll
            for (int nf = 0; nf < 6; nf++) {
                mma_f16(acc[0][nf], ah0[0], ah0[1], ah0[2], ah0[3], bv[nf].z, bv[nf].w);
                mma_f16(acc[1][nf], ah1[0], ah1[1], ah1[2], ah1[3], bv[nf].z, bv[nf].w);
            }
        }
        LOAD_STAGE(kl);            // LDG prefetch for chunk kc+2
        asm volatile("cp.async.wait_group 0;" ::: "memory");
        __syncthreads();
    }

    // ---- epilogue: relu(y1) -> fp16 [128 rows][112 halfs] (overlays stages) ----
#pragma unroll
    for (int im = 0; im < 2; im++) {
        int m0 = (mb0 + im) * 16 + fr;
        int m1 = m0 + 8;
#pragma unroll
        for (int nf = 0; nf < 6; nf++) {
            int nb = (nh * 6 + nf) * 8 + ql * 2;
            *(u32*)(sm + (m0 * 112 + nb) * 2) =
                pack_half(fmaxf(acc[im][nf][0], 0.f), fmaxf(acc[im][nf][1], 0.f));
            *(u32*)(sm + (m1 * 112 + nb) * 2) =
                pack_half(fmaxf(acc[im][nf][2], 0.f), fmaxf(acc[im][nf][3], 0.f));
        }
    }
    // tail weights into overlay region (disjoint from y1 fp16)
    for (int i = tid; i < 4608; i += 256) { wf[OW2E + i] = eW2[i]; wf[OW2S + i] = sW2[i]; }
    for (int i = tid; i < 1152; i += 256) { wf[OW3E + i] = eW3[i]; wf[OW3S + i] = sW3[i]; }
    if (tid < 144) { wf[OW4E + tid] = eW4[tid]; wf[OW4E + 144 + tid] = eW4[144 + tid];
                     wf[OW4S + tid] = sW4[tid]; wf[OW4S + 144 + tid] = sW4[144 + tid]; }
    if (tid >= 160 && tid < 184) wf[OW5 + tid - 160] = sW5[tid - 160];
    if (tid >= 192 && tid < 204) {
        int k = tid - 192; float s = 0.f;
#pragma unroll
        for (int h = 0; h < 8; h++) s += eW5[h * 12 + k];
        wf[OE5 + k] = s;
    }
    __syncthreads();

    // ---- tail: 2 threads per vector, k-split + shfl combine ----
    {
        const int m  = tid >> 1;           // 0..127 vec row
        const int kh = tid & 1;            // k half
        const bool is_e = m < 64;
        const int r  = (m & 63) >> 1;
        const int vp = m & 1;

        // load 48 fp16 y1 values (this thread's k-half), widen to f32 pairs
        u64t x[24];
        {
            const u32 xb = (u32)(m * 224 + kh * 96);
#pragma unroll
            for (int i = 0; i < 6; i++) {
                uint4 v = *(const uint4*)(sm + xb + i * 16);
                float2 f;
                f = __half22float2(*(const __half2*)&v.x); x[i*4+0] = pack2(f.x, f.y);
                f = __half22float2(*(const __half2*)&v.y); x[i*4+1] = pack2(f.x, f.y);
                f = __half22float2(*(const __half2*)&v.z); x[i*4+2] = pack2(f.x, f.y);
                f = __half22float2(*(const __half2*)&v.w); x[i*4+3] = pack2(f.x, f.y);
            }
        }

        const float* W2 = wf + (is_e ? OW2E : OW2S) + kh * 48;
        float y2r[48];
#pragma unroll 4
        for (int n = 0; n < 48; n++) {
            const u64t* wr = (const u64t*)(W2 + n * 96);
            u64t s0 = 0, s1 = 0;
#pragma unroll
            for (int kp = 0; kp < 24; kp += 2) {
                s0 = fma2(x[kp], wr[kp], s0);
                s1 = fma2(x[kp + 1], wr[kp + 1], s1);
            }
            float s = red2(s0) + red2(s1);
            s += __shfl_xor_sync(0xffffffffu, s, 1);
            y2r[n] = fmaxf(s, 0.f);
        }

        u64t b2[12];
#pragma unroll
        for (int j = 0; j < 12; j++) b2[j] = pack2(y2r[kh * 24 + 2 * j], y2r[kh * 24 + 2 * j + 1]);
        const float* W3 = wf + (is_e ? OW3E : OW3S) + kh * 24;
        float y3r[24];
#pragma unroll
        for (int n = 0; n < 24; n++) {
            const u64t* wr = (const u64t*)(W3 + n * 48);
            u64t s0 = 0;
#pragma unroll
            for (int kp = 0; kp < 12; kp++) s0 = fma2(b2[kp], wr[kp], s0);
            float s = red2(s0);
            s += __shfl_xor_sync(0xffffffffu, s, 1);
            y3r[n] = fmaxf(s, 0.f);
        }

        u64t b3[6];
#pragma unroll
        for (int j = 0; j < 6; j++) b3[j] = pack2(y3r[kh * 12 + 2 * j], y3r[kh * 12 + 2 * j + 1]);
        const float* W4 = wf + (is_e ? OW4E : OW4S) + kh * 12;
        float r4[12];
#pragma unroll
        for (int n = 0; n < 12; n++) {
            const u64t* wr = (const u64t*)(W4 + n * 24);
            u64t s0 = 0;
#pragma unroll
            for (int kp = 0; kp < 6; kp++) s0 = fma2(b3[kp], wr[kp], s0);
            float s = red2(s0);
            s += __shfl_xor_sync(0xffffffffu, s, 1);
            r4[n] = fmaxf(s, 0.f);       // relu before W5
        }

        if (kh == 0) {
            const int idx2 = r * 2 + vp;
            if (is_e) {
                float Se = 0.f;
#pragma unroll
                for (int k = 0; k < 12; k++) Se = fmaf(r4[k], wf[OE5 + k], Se);
                wf[OSE + idx2] = Se;
            } else {
                float t0 = 0.f, t1 = 0.f;
#pragma unroll
                for (int k = 0; k < 12; k++) {
                    t0 = fmaf(r4[k], wf[OW5 + k], t0);
                    t1 = fmaf(r4[k], wf[OW5 + 12 + k], t1);
                }
                wf[OT0 + idx2] = t0;
                wf[OT1 + idx2] = t1;
            }
        }
    }
    __syncthreads();

    if (tid < 32) {
        const int r = tid;
        const float cw0 = cross_w[0], cw1 = cross_w[1];
        float SeP = wf[OSE + 2*r], SeS = wf[OSE + 2*r + 1];
        float o0 = cw0 * SeP * wf[OT0 + 2*r] + cw1 * SeS * wf[OT0 + 2*r + 1];
        float o1 = cw0 * SeP * wf[OT1 + 2*r] + cw1 * SeS * wf[OT1 + 2*r + 1];
        out[(size_t)(r0g + r) * 2 + 0] = o0;
        out[(size_t)(r0g + r) * 2 + 1] = o1;
    }
}

// ============================================================================
extern "C" void kernel_launch(void* const* d_in, const int* in_sizes, int n_in,
                              void* d_out, int out_size)
{
    const float* in      = (const float*)d_in[0];
    const float* sW1     = (const float*)d_in[1];
    const float* sW2     = (const float*)d_in[2];
    const float* sW3     = (const float*)d_in[3];
    const float* sW4     = (const float*)d_in[4];
    const float* sW5     = (const float*)d_in[5];
    const float* eW1     = (const float*)d_in[6];
    const float* eW2     = (const float*)d_in[7];
    const float* eW3     = (const float*)d_in[8];
    const float* eW4     = (const float*)d_in[9];
    const float* eW5     = (const float*)d_in[10];
    const float* s_seq   = (const float*)d_in[11];
    const float* s_pair  = (const float*)d_in[12];
    const float* e_seq   = (const float*)d_in[13];
    const float* e_pair  = (const float*)d_in[14];
    const float* cross_w = (const float*)d_in[15];
    float* out = (float*)d_out;

    const int B = in_sizes[0] / 3072;   // 65536

    static int init_done = 0;
    if (!init_done) {
        cudaFuncSetAttribute(fused_mma, cudaFuncAttributeMaxDynamicSharedMemorySize, SMEM_BYTES);
        init_done = 1;
    }
    prep_w1<<<72, 256>>>(eW1, sW1);
    fused_mma<<<B / 32, 256, SMEM_BYTES>>>(
        in, sW2, sW3, sW4, sW5, eW2, eW3, eW4, eW5,
        s_seq, s_pair, e_seq, e_pair, cross_w, out);
}

// round 17
// speedup vs baseline: 1.3019x; 1.0445x over previous
#include <cuda_runtime.h>
#include <cuda_fp16.h>
#include <cstdint>

typedef unsigned int u32;
typedef unsigned long long u64t;

// ============================================================================
// g_prep: packed, fragment-ordered fp16 W1 (single precision weights).
// [kc 0..23][br 0..1][n 0..95][q 0..3] -> 16B uint4 (both k16 steps of a 32-k block)
// Two consecutive kc blocks = one contiguous 24 KB K=64 chunk.
// ============================================================================
__device__ __align__(16) u32 g_prep[24 * 2 * 96 * 16];   // 294912 B

__device__ __forceinline__ u32 pack_half(float a, float b) {
    __half2 h = __floats2half2_rn(a, b);
    return *(u32*)&h;
}

__global__ void prep_w1(const float* __restrict__ eW1, const float* __restrict__ sW1)
{
    int idx = blockIdx.x * 256 + threadIdx.x;        // 0 .. 18431
    if (idx >= 18432) return;
    int q  = idx & 3;
    int n  = (idx >> 2) % 96;
    int t  = (idx >> 2) / 96;
    int kc = t % 24;
    int br = t / 24;
    const float* W = (br ? sW1 : eW1) + (size_t)n * 768 + kc * 32;
    uint4 v;
    v.x = pack_half(W[2*q],      W[2*q+1]);
    v.y = pack_half(W[8+2*q],    W[8+2*q+1]);
    v.z = pack_half(W[16+2*q],   W[16+2*q+1]);
    v.w = pack_half(W[24+2*q],   W[24+2*q+1]);
    u32 off = (u32)kc * 12288 + (u32)br * 6144 + (u32)n * 64 + (u32)q * 16;
    *(uint4*)((char*)g_prep + off) = v;
}

// ============================================================================
// helpers
// ============================================================================
__device__ __forceinline__ u32 smem_u32(const void* p) {
    u32 a;
    asm("{ .reg .u64 t; cvta.to.shared.u64 t, %1; cvt.u32.u64 %0, t; }" : "=r"(a) : "l"(p));
    return a;
}
__device__ __forceinline__ u64t fma2(u64t a, u64t b, u64t c) {
    u64t d;
    asm("fma.rn.f32x2 %0, %1, %2, %3;" : "=l"(d) : "l"(a), "l"(b), "l"(c));
    return d;
}
__device__ __forceinline__ float red2(u64t v) {
    return __uint_as_float((u32)v) + __uint_as_float((u32)(v >> 32));
}
__device__ __forceinline__ u64t pack2(float lo, float hi) {
    return (u64t)__float_as_uint(lo) | ((u64t)__float_as_uint(hi) << 32);
}
__device__ __forceinline__ u64t half4(float4 q) {
    __half2 h01 = __floats2half2_rn(q.x, q.y);
    __half2 h23 = __floats2half2_rn(q.z, q.w);
    return (u64t)(*(u32*)&h01) | ((u64t)(*(u32*)&h23) << 32);
}
__device__ __forceinline__ void mma_f16(float c[4], u32 a0, u32 a1, u32 a2, u32 a3,
                                        u32 b0, u32 b1) {
    asm volatile("mma.sync.aligned.m16n8k16.row.col.f32.f16.f16.f32 "
        "{%0,%1,%2,%3}, {%4,%5,%6,%7}, {%8,%9}, {%0,%1,%2,%3};"
        : "+f"(c[0]), "+f"(c[1]), "+f"(c[2]), "+f"(c[3])
        : "r"(a0), "r"(a1), "r"(a2), "r"(a3), "r"(b0), "r"(b1));
}
#define LDSM_X4(d0, d1, d2, d3, a) \
    asm volatile("ldmatrix.sync.aligned.m8n8.x4.shared.b16 {%0,%1,%2,%3}, [%4];" \
        : "=r"(d0), "=r"(d1), "=r"(d2), "=r"(d3) : "r"(a))

// ============================================================================
// smem layout (bytes), per 256-thread CTA (2 CTAs/SM), K=64 chunks
//   A stages: stage*18432 (128 vec rows * 144B row stride, fp16)
//   B stages: 36864 + stage*24576  -> ends 86016
//   tail overlay: y1 fp16 [0, 28672) = 128 rows * 112 halfs ; weights at 28672
// ============================================================================
#define A_STAGE 18432
#define SM_B0   36864
#define B_STAGE 24576
#define SM_W    28672
#define SMEM_BYTES 86016
// weight region float offsets (from sm + SM_W)
#define OW2E 0
#define OW2S 4608
#define OW3E 9216
#define OW3S 10368
#define OW4E 11520
#define OW4S 11808
#define OW5  12096
#define OE5  12120
#define OSE  12132
#define OT0  12196
#define OT1  12260

__global__ __launch_bounds__(256, 2) void fused_mma(
    const float* __restrict__ in,
    const float* __restrict__ sW2, const float* __restrict__ sW3,
    const float* __restrict__ sW4, const float* __restrict__ sW5,
    const float* __restrict__ eW2, const float* __restrict__ eW3,
    const float* __restrict__ eW4, const float* __restrict__ eW5,
    const float* __restrict__ s_seq, const float* __restrict__ s_pair,
    const float* __restrict__ e_seq, const float* __restrict__ e_pair,
    const float* __restrict__ cross_w,
    float* __restrict__ out)
{
    extern __shared__ __align__(1024) char sm[];
    float* wf = (float*)(sm + SM_W);

    const int tid = threadIdx.x;
    const int r0g = blockIdx.x * 32;

    const float ep0 = e_pair[0], ep1 = e_pair[1];
    const float sp0 = s_pair[0], sp1 = s_pair[1];
    const float es0 = e_seq[0], es1 = e_seq[1], es2 = e_seq[2], es3 = e_seq[3];
    const float ss0 = s_seq[0], ss1 = s_seq[1], ss2 = s_seq[2], ss3 = s_seq[3];

    // ---- builder mapping: 32 rows across 256 threads ----
    const int rb = tid >> 3;           // 0..31 batch row
    const int sk = tid & 7;            // float4 group within a 32-k half
    const float* inp0 = in + (size_t)(r0g + rb) * 3072 + sk * 4;

    // ---- mma mapping: 8 warps, warp = m32 x n48 ----
    const int lane = tid & 31;
    const int w    = tid >> 5;          // 0..7
    const int br   = w >> 2;            // 0=e, 1=s
    const int wm   = (w >> 1) & 1;      // m32 group within branch
    const int nh   = w & 1;             // n half
    const int fr   = lane >> 2;
    const int ql   = lane & 3;
    const int mb0  = br * 4 + wm * 2;   // first m16 block (0..7)

    // ldmatrix lane addressing (canonical m16k16 x4)
    const u32 lrow = (u32)((lane & 7) | (((lane >> 3) & 1) << 3));   // 0..15
    const u32 lkb  = (u32)((lane >> 4) * 16);                        // 0 or 16 B

    u64t gprep;
    asm("cvta.to.global.u64 %0, %1;" : "=l"(gprep) : "l"((const void*)g_prep));
    const u32 smbase = smem_u32(sm);
    const u32 b_sm = smbase + SM_B0;
    const u32 awarp = (u32)(mb0 * 16 + lrow) * 144 + lkb;

    float acc[2][6][4];
#pragma unroll
    for (int im = 0; im < 2; im++)
#pragma unroll
        for (int nf = 0; nf < 6; nf++)
#pragma unroll
            for (int c = 0; c < 4; c++) acc[im][nf][c] = 0.f;

    // two staging sets: half0 (A) and half1 (B) of a K=64 chunk
    float4 hA0, hA1, hA2, hA3, hB0, hB1, hB2, hB3;

#define LOAD_HALF_A(kcv) { \
    const float* p0 = inp0 + (kcv) * 64; \
    hA0 = __ldcg((const float4*)p0);          hA1 = __ldcg((const float4*)(p0 + 768)); \
    hA2 = __ldcg((const float4*)(p0 + 1536)); hA3 = __ldcg((const float4*)(p0 + 2304)); }
#define LOAD_HALF_B(kcv) { \
    const float* p0 = inp0 + (kcv) * 64 + 32; \
    hB0 = __ldcg((const float4*)p0);          hB1 = __ldcg((const float4*)(p0 + 768)); \
    hB2 = __ldcg((const float4*)(p0 + 1536)); hB3 = __ldcg((const float4*)(p0 + 2304)); }

// build one 32-k half (4 pooled vecs) from the given staged regs
#define BUILD_HALF(stage, half, t0, t1, t2, t3) { \
    u32 off = (u32)(stage) * A_STAGE + (u32)(rb * 2) * 144 + (u32)(half) * 64 + (u32)sk * 8; \
    float4 q; \
    q.x = fmaxf(ep0*t0.x + ep1*t2.x, 0.f); q.y = fmaxf(ep0*t0.y + ep1*t2.y, 0.f); \
    q.z = fmaxf(ep0*t0.z + ep1*t2.z, 0.f); q.w = fmaxf(ep0*t0.w + ep1*t2.w, 0.f); \
    *(u64t*)(sm + off) = half4(q); \
    q.x = fmaxf(es0*t0.x + es1*t1.x + es2*t2.x + es3*t3.x, 0.f); \
    q.y = fmaxf(es0*t0.y + es1*t1.y + es2*t2.y + es3*t3.y, 0.f); \
    q.z = fmaxf(es0*t0.z + es1*t1.z + es2*t2.z + es3*t3.z, 0.f); \
    q.w = fmaxf(es0*t0.w + es1*t1.w + es2*t2.w + es3*t3.w, 0.f); \
    *(u64t*)(sm + off + 144) = half4(q); \
    q.x = fmaxf(sp0*t0.x + sp1*t2.x, 0.f); q.y = fmaxf(sp0*t0.y + sp1*t2.y, 0.f); \
    q.z = fmaxf(sp0*t0.z + sp1*t2.z, 0.f); q.w = fmaxf(sp0*t0.w + sp1*t2.w, 0.f); \
    *(u64t*)(sm + off + 9216) = half4(q); \
    q.x = fmaxf(ss0*t0.x + ss1*t1.x + ss2*t2.x + ss3*t3.x, 0.f); \
    q.y = fmaxf(ss0*t0.y + ss1*t1.y + ss2*t2.y + ss3*t3.y, 0.f); \
    q.z = fmaxf(ss0*t0.z + ss1*t1.z + ss2*t2.z + ss3*t3.z, 0.f); \
    q.w = fmaxf(ss0*t0.w + ss1*t1.w + ss2*t2.w + ss3*t3.w, 0.f); \
    *(u64t*)(sm + off + 9360) = half4(q); }

#define CPASYNC_B(stage, kcv) { \
    u64t gs = gprep + (u64t)(kcv) * 24576; \
    u32 db = b_sm + (u32)(stage) * B_STAGE; \
    _Pragma("unroll") \
    for (int j = 0; j < 6; j++) { \
        u32 i = (u32)tid * 16 + (u32)j * 4096; \
        asm volatile("cp.async.cg.shared.global [%0], [%1], 16;" \
                     :: "r"(db + i), "l"(gs + i) : "memory"); \
    } \
    asm volatile("cp.async.commit_group;" ::: "memory"); }

// MMA over one 32-k block (2 k16 steps) of stage `cur`
#define MMA_BLOCK(blk) { \
    uint4 bv[6]; \
    u32 bb = b_sm + (u32)cur * B_STAGE + (u32)(blk) * 12288 \
           + (u32)(br * 6144 + nh * 3072) + (u32)fr * 64 + (u32)ql * 16; \
    _Pragma("unroll") \
    for (int nf = 0; nf < 6; nf++) \
        bv[nf] = *(const uint4*)(sm + (bb - smbase) + nf * 512); \
    _Pragma("unroll") \
    for (int ks = 0; ks < 2; ks++) { \
        u32 aB = smbase + (u32)cur * A_STAGE + awarp + (u32)(blk) * 64 + (u32)ks * 32; \
        u32 ah0[4], ah1[4]; \
        LDSM_X4(ah0[0], ah0[1], ah0[2], ah0[3], aB); \
        LDSM_X4(ah1[0], ah1[1], ah1[2], ah1[3], aB + 2304); \
        _Pragma("unroll") \
        for (int nf = 0; nf < 6; nf++) { \
            u32 b0 = ks ? bv[nf].z : bv[nf].x; \
            u32 b1 = ks ? bv[nf].w : bv[nf].y; \
            mma_f16(acc[0][nf], ah0[0], ah0[1], ah0[2], ah0[3], b0, b1); \
            mma_f16(acc[1][nf], ah1[0], ah1[1], ah1[2], ah1[3], b0, b1); \
        } \
    } }

    // ---- prologue: fill stage 0, stage regs for chunk 1 ----
    LOAD_HALF_A(0);
    LOAD_HALF_B(0);
    BUILD_HALF(0, 0, hA0, hA1, hA2, hA3);
    BUILD_HALF(0, 1, hB0, hB1, hB2, hB3);
    CPASYNC_B(0, 0);
    LOAD_HALF_A(1);
    LOAD_HALF_B(1);
    asm volatile("cp.async.wait_group 0;" ::: "memory");
    __syncthreads();

    // ---- mainloop: 12 K=64 chunks ----
    for (int kc = 0; kc < 12; kc++) {
        const int cur = kc & 1, nxt = cur ^ 1;
        const int kn = (kc < 11) ? kc + 1 : 11;
        const int kl = (kc < 10) ? kc + 2 : 11;

        CPASYNC_B(nxt, kn);                       // B for next chunk
        MMA_BLOCK(0);                             // k 0..31 of cur
        BUILD_HALF(nxt, 0, hA0, hA1, hA2, hA3);   // A half0 of next chunk
        MMA_BLOCK(1);                             // k 32..63 of cur
        BUILD_HALF(nxt, 1, hB0, hB1, hB2, hB3);   // A half1 of next chunk
        LOAD_HALF_A(kl);                          // LDG prefetch for chunk kc+2
        LOAD_HALF_B(kl);
        asm volatile("cp.async.wait_group 0;" ::: "memory");
        __syncthreads();
    }

    // ---- epilogue: relu(y1) -> fp16 [128 rows][112 halfs] (overlays stages) ----
#pragma unroll
    for (int im = 0; im < 2; im++) {
        int m0 = (mb0 + im) * 16 + fr;
        int m1 = m0 + 8;
#pragma unroll
        for (int nf = 0; nf < 6; nf++) {
            int nb = (nh * 6 + nf) * 8 + ql * 2;
            *(u32*)(sm + (m0 * 112 + nb) * 2) =
                pack_half(fmaxf(acc[im][nf][0], 0.f), fmaxf(acc[im][nf][1], 0.f));
            *(u32*)(sm + (m1 * 112 + nb) * 2) =
                pack_half(fmaxf(acc[im][nf][2], 0.f), fmaxf(acc[im][nf][3], 0.f));
        }
    }
    // tail weights into overlay region (disjoint from y1 fp16)
    for (int i = tid; i < 4608; i += 256) { wf[OW2E + i] = eW2[i]; wf[OW2S + i] = sW2[i]; }
    for (int i = tid; i < 1152; i += 256) { wf[OW3E + i] = eW3[i]; wf[OW3S + i] = sW3[i]; }
    if (tid < 144) { wf[OW4E + tid] = eW4[tid]; wf[OW4E + 144 + tid] = eW4[144 + tid];
                     wf[OW4S + tid] = sW4[tid]; wf[OW4S + 144 + tid] = sW4[144 + tid]; }
    if (tid >= 160 && tid < 184) wf[OW5 + tid - 160] = sW5[tid - 160];
    if (tid >= 192 && tid < 204) {
        int k = tid - 192; float s = 0.f;
#pragma unroll
        for (int h = 0; h < 8; h++) s += eW5[h * 12 + k];
        wf[OE5 + k] = s;
    }
    __syncthreads();

    // ---- tail: 2 threads per vector, k-split + shfl combine ----
    {
        const int m  = tid >> 1;           // 0..127 vec row
        const int kh = tid & 1;            // k half
        const bool is_e = m < 64;
        const int r  = (m & 63) >> 1;
        const int vp = m & 1;

        // load 48 fp16 y1 values (this thread's k-half), widen to f32 pairs
        u64t x[24];
        {
            const u32 xb = (u32)(m * 224 + kh * 96);
#pragma unroll
            for (int i = 0; i < 6; i++) {
                uint4 v = *(const uint4*)(sm + xb + i * 16);
                float2 f;
                f = __half22float2(*(const __half2*)&v.x); x[i*4+0] = pack2(f.x, f.y);
                f = __half22float2(*(const __half2*)&v.y); x[i*4+1] = pack2(f.x, f.y);
                f = __half22float2(*(const __half2*)&v.z); x[i*4+2] = pack2(f.x, f.y);
                f = __half22float2(*(const __half2*)&v.w); x[i*4+3] = pack2(f.x, f.y);
            }
        }

        const float* W2 = wf + (is_e ? OW2E : OW2S) + kh * 48;
        float y2r[48];
#pragma unroll 4
        for (int n = 0; n < 48; n++) {
            const u64t* wr = (const u64t*)(W2 + n * 96);
            u64t s0 = 0, s1 = 0;
#pragma unroll
            for (int kp = 0; kp < 24; kp += 2) {
                s0 = fma2(x[kp], wr[kp], s0);
                s1 = fma2(x[kp + 1], wr[kp + 1], s1);
            }
            float s = red2(s0) + red2(s1);
            s += __shfl_xor_sync(0xffffffffu, s, 1);
            y2r[n] = fmaxf(s, 0.f);
        }

        u64t b2[12];
#pragma unroll
        for (int j = 0; j < 12; j++) b2[j] = pack2(y2r[kh * 24 + 2 * j], y2r[kh * 24 + 2 * j + 1]);
        const float* W3 = wf + (is_e ? OW3E : OW3S) + kh * 24;
        float y3r[24];
#pragma unroll
        for (int n = 0; n < 24; n++) {
            const u64t* wr = (const u64t*)(W3 + n * 48);
            u64t s0 = 0;
#pragma unroll
            for (int kp = 0; kp < 12; kp++) s0 = fma2(b2[kp], wr[kp], s0);
            float s = red2(s0);
            s += __shfl_xor_sync(0xffffffffu, s, 1);
            y3r[n] = fmaxf(s, 0.f);
        }

        u64t b3[6];
#pragma unroll
        for (int j = 0; j < 6; j++) b3[j] = pack2(y3r[kh * 12 + 2 * j], y3r[kh * 12 + 2 * j + 1]);
        const float* W4 = wf + (is_e ? OW4E : OW4S) + kh * 12;
        float r4[12];
#pragma unroll
        for (int n = 0; n < 12; n++) {
            const u64t* wr = (const u64t*)(W4 + n * 24);
            u64t s0 = 0;
#pragma unroll
            for (int kp = 0; kp < 6; kp++) s0 = fma2(b3[kp], wr[kp], s0);
            float s = red2(s0);
            s += __shfl_xor_sync(0xffffffffu, s, 1);
            r4[n] = fmaxf(s, 0.f);       // relu before W5
        }

        if (kh == 0) {
            const int idx2 = r * 2 + vp;
            if (is_e) {
                float Se = 0.f;
#pragma unroll
                for (int k = 0; k < 12; k++) Se = fmaf(r4[k], wf[OE5 + k], Se);
                wf[OSE + idx2] = Se;
            } else {
                float t0 = 0.f, t1 = 0.f;
#pragma unroll
                for (int k = 0; k < 12; k++) {
                    t0 = fmaf(r4[k], wf[OW5 + k], t0);
                    t1 = fmaf(r4[k], wf[OW5 + 12 + k], t1);
                }
                wf[OT0 + idx2] = t0;
                wf[OT1 + idx2] = t1;
            }
        }
    }
    __syncthreads();

    if (tid < 32) {
        const int r = tid;
        const float cw0 = cross_w[0], cw1 = cross_w[1];
        float SeP = wf[OSE + 2*r], SeS = wf[OSE + 2*r + 1];
        float o0 = cw0 * SeP * wf[OT0 + 2*r] + cw1 * SeS * wf[OT0 + 2*r + 1];
        float o1 = cw0 * SeP * wf[OT1 + 2*r] + cw1 * SeS * wf[OT1 + 2*r + 1];
        out[(size_t)(r0g + r) * 2 + 0] = o0;
        out[(size_t)(r0g + r) * 2 + 1] = o1;
    }
}

// ============================================================================
extern "C" void kernel_launch(void* const* d_in, const int* in_sizes, int n_in,
                              void* d_out, int out_size)
{
    const float* in      = (const float*)d_in[0];
    const float* sW1     = (const float*)d_in[1];
    const float* sW2     = (const float*)d_in[2];
    const float* sW3     = (const float*)d_in[3];
    const float* sW4     = (const float*)d_in[4];
    const float* sW5     = (const float*)d_in[5];
    const float* eW1     = (const float*)d_in[6];
    const float* eW2     = (const float*)d_in[7];
    const float* eW3     = (const float*)d_in[8];
    const float* eW4     = (const float*)d_in[9];
    const float* eW5     = (const float*)d_in[10];
    const float* s_seq   = (const float*)d_in[11];
    const float* s_pair  = (const float*)d_in[12];
    const float* e_seq   = (const float*)d_in[13];
    const float* e_pair  = (const float*)d_in[14];
    const float* cross_w = (const float*)d_in[15];
    float* out = (float*)d_out;

    const int B = in_sizes[0] / 3072;   // 65536

    static int init_done = 0;
    if (!init_done) {
        cudaFuncSetAttribute(fused_mma, cudaFuncAttributeMaxDynamicSharedMemorySize, SMEM_BYTES);
        init_done = 1;
    }
    prep_w1<<<72, 256>>>(eW1, sW1);
    fused_mma<<<B / 32, 256, SMEM_BYTES>>>(
        in, sW2, sW3, sW4, sW5, eW2, eW3, eW4, eW5,
        s_seq, s_pair, e_seq, e_pair, cross_w, out);
}